// round 6
// baseline (speedup 1.0000x reference)
#include <cuda_runtime.h>

// SSIM loss: B=64, C=2, H=W=320, WIN=7 (VALID), channel-summing uniform window.
// out = 1 - mean(S), S per output pixel [64,1,314,314].

#define Hh 320
#define Ww 320
#define OH 314
#define OW 314
#define Bb 64
#define CHUNK 45
#define NCHUNK 7
#define NBLOCKS (Bb * NCHUNK)
#define NPIX (64.0 * 314.0 * 314.0)
#define GROUP 4
#define CH_OFF (Hh * Ww)   // channel stride in elements (102400)

__device__ float g_partials[NBLOCKS];
__device__ unsigned int g_count = 0;

__global__ __launch_bounds__(320, 3) void ssim_main(
    const float* __restrict__ X, const float* __restrict__ Y,
    const float* __restrict__ data_range, const float* __restrict__ w,
    float* __restrict__ out) {
    const int t = threadIdx.x;       // input column 0..319
    const int chunk = blockIdx.x;    // 0..6
    const int b = blockIdx.y;        // 0..63
    const int y0 = chunk * CHUNK;
    const int R = min(CHUNK, OH - y0);           // 45, except last chunk: 44

    const float w0 = w[0];                       // uniform weight (1/49)
    const float dr = data_range[b];
    const float C1 = (0.01f * dr) * (0.01f * dr);
    const float C2 = (0.03f * dr) * (0.03f * dr);
    const float cn = 49.0f / 48.0f;              // COV_NORM

    const float* __restrict__ Xb = X + (size_t)b * 2 * CH_OFF;
    const float* __restrict__ Yb = Y + (size_t)b * 2 * CH_OFF;

    __shared__ __align__(16) float sm[GROUP][5][336];
    __shared__ float red[320];
    __shared__ int s_islast;

    // zero the pad region of sm once (read by tail float4 loads)
    if (t < 16) {
#pragma unroll
        for (int r = 0; r < GROUP; ++r)
#pragma unroll
            for (int s = 0; s < 5; ++s) sm[r][s][320 + t] = 0.0f;
    }

    // 6-slot shift ring of RAW inputs (x0,x1,ya,yb) + running vertical sums.
    float rx0[6], rx1[6], rya[6], ryb[6];
    float vsum[5];
#pragma unroll
    for (int s = 0; s < 5; ++s) vsum[s] = 0.0f;

    // prologue: input rows y0 .. y0+5 -> ring slots 0..5
#pragma unroll
    for (int r = 0; r < 6; ++r) {
        const int off = (y0 + r) * Ww + t;
        float x0 = Xb[off], x1 = Xb[off + CH_OFF];
        float ya = Yb[off], yb = Yb[off + CH_OFF];
        rx0[r] = x0; rx1[r] = x1; rya[r] = ya; ryb[r] = yb;
        vsum[0] += x0 + x1;
        vsum[1] += ya + yb;
        vsum[2] += fmaf(x0, x0, x1 * x1);
        vsum[3] += fmaf(ya, ya, yb * yb);
        vsum[4] += fmaf(x0, ya, x1 * yb);
    }

    float acc = 0.0f;
    const int hr = t / 80;           // horizontal-phase row within group
    const int hj = t % 80;
    const int c0 = hj * 4;           // horizontal-phase base column
    const int G = (R + GROUP - 1) / GROUP;

    __syncthreads();                 // pad zero visible

    for (int g = 0; g < G; ++g) {
        // ---- group loads: 4 rows x 4 values, issued together (MLP 16) ----
        float g4[GROUP][4];
#pragma unroll
        for (int r = 0; r < GROUP; ++r) {
            const int k = GROUP * g + r;
            if (k < R) {
                const int off = (y0 + 6 + k) * Ww + t;
                g4[r][0] = Xb[off]; g4[r][1] = Xb[off + CH_OFF];
                g4[r][2] = Yb[off]; g4[r][3] = Yb[off + CH_OFF];
            } else {
                g4[r][0] = g4[r][1] = g4[r][2] = g4[r][3] = 0.0f;
            }
        }

        // ---- vertical phase: 4 rows of column sums ----
#pragma unroll
        for (int r = 0; r < GROUP; ++r) {
            const int k = GROUP * g + r;
            if (k < R) {
                float x0 = g4[r][0], x1 = g4[r][1];
                float ya = g4[r][2], yb = g4[r][3];
                vsum[0] += x0 + x1;
                vsum[1] += ya + yb;
                vsum[2] += fmaf(x0, x0, x1 * x1);
                vsum[3] += fmaf(ya, ya, yb * yb);
                vsum[4] += fmaf(x0, ya, x1 * yb);
                sm[r][0][t] = vsum[0];
                sm[r][1][t] = vsum[1];
                sm[r][2][t] = vsum[2];
                sm[r][3][t] = vsum[3];
                sm[r][4][t] = vsum[4];
                // retire oldest raw row (recompute its stats), shift, append
                float o0 = rx0[0], o1 = rx1[0], oa = rya[0], ob = ryb[0];
                vsum[0] -= o0 + o1;
                vsum[1] -= oa + ob;
                vsum[2] -= fmaf(o0, o0, o1 * o1);
                vsum[3] -= fmaf(oa, oa, ob * ob);
                vsum[4] -= fmaf(o0, oa, o1 * ob);
#pragma unroll
                for (int i = 0; i < 5; ++i) {
                    rx0[i] = rx0[i + 1]; rx1[i] = rx1[i + 1];
                    rya[i] = rya[i + 1]; ryb[i] = ryb[i + 1];
                }
                rx0[5] = x0; rx1[5] = x1; rya[5] = ya; ryb[5] = yb;
            }
        }

        __syncthreads();   // column sums visible

        // ---- horizontal phase: all 320 threads (4 rows x 80 col-groups) ----
        {
            const int k = GROUP * g + hr;
            if (k < R) {
                float h[5][4];
#pragma unroll
                for (int s = 0; s < 5; ++s) {
                    const float4 va = *(const float4*)&sm[hr][s][c0];
                    const float4 vb = *(const float4*)&sm[hr][s][c0 + 4];
                    const float4 vc = *(const float4*)&sm[hr][s][c0 + 8];
                    float h0 = va.x + va.y + va.z + va.w + vb.x + vb.y + vb.z;
                    float h1 = h0 - va.x + vb.w;
                    float h2 = h1 - va.y + vc.x;
                    float h3 = h2 - va.z + vc.y;
                    h[s][0] = h0; h[s][1] = h1; h[s][2] = h2; h[s][3] = h3;
                }
#pragma unroll
                for (int i = 0; i < 4; ++i) {
                    if (c0 + i < OW) {
                        float ux  = w0 * h[0][i];
                        float uy  = w0 * h[1][i];
                        float uxx = w0 * h[2][i];
                        float uyy = w0 * h[3][i];
                        float uxy = w0 * h[4][i];
                        float vx  = cn * (uxx - ux * ux);
                        float vy  = cn * (uyy - uy * uy);
                        float vxy = cn * (uxy - ux * uy);
                        float A1 = 2.0f * ux * uy + C1;
                        float A2 = 2.0f * vxy + C2;
                        float B1 = ux * ux + uy * uy + C1;
                        float B2 = vx + vy + C2;
                        acc += __fdividef(A1 * A2, B1 * B2);
                    }
                }
            }
        }

        __syncthreads();   // horizontal reads done before next vertical writes
    }

    // ---- block reduction of acc (fixed order -> deterministic) ----
    red[t] = acc;
    __syncthreads();
    if (t < 160) red[t] += red[t + 160];
    __syncthreads();
    if (t < 80) red[t] += red[t + 80];
    __syncthreads();
    if (t < 40) red[t] += red[t + 40];
    __syncthreads();
    if (t < 20) red[t] += red[t + 20];
    __syncthreads();
    if (t < 10) red[t] += red[t + 10];
    __syncthreads();
    if (t < 5) red[t] += red[t + 5];
    __syncthreads();

    if (t == 0) {
        float v = red[0] + red[1] + red[2] + red[3] + red[4];
        g_partials[b * NCHUNK + chunk] = v;
        __threadfence();
        unsigned int old = atomicAdd(&g_count, 1u);
        s_islast = (old == NBLOCKS - 1);
    }
    __syncthreads();

    // ---- last block finishes the global reduction (deterministic order) ----
    if (s_islast) {
        __threadfence();
        float v = g_partials[t];
        if (t < NBLOCKS - 320) v += g_partials[t + 320];
        red[t] = v;
        __syncthreads();
        if (t < 160) red[t] += red[t + 160];
        __syncthreads();
        if (t < 80) red[t] += red[t + 80];
        __syncthreads();
        if (t < 40) red[t] += red[t + 40];
        __syncthreads();
        if (t < 20) red[t] += red[t + 20];
        __syncthreads();
        if (t < 10) red[t] += red[t + 10];
        __syncthreads();
        if (t < 5) red[t] += red[t + 5];
        __syncthreads();
        if (t == 0) {
            double total = (double)(red[0] + red[1] + red[2] + red[3] + red[4]);
            out[0] = (float)(1.0 - total / NPIX);
            g_count = 0;   // reset for next graph replay
        }
    }
}

extern "C" void kernel_launch(void* const* d_in, const int* in_sizes, int n_in,
                              void* d_out, int out_size) {
    const float* X  = (const float*)d_in[0];
    const float* Y  = (const float*)d_in[1];
    const float* dr = (const float*)d_in[2];
    const float* w  = (const float*)d_in[3];
    dim3 grid(NCHUNK, Bb);
    ssim_main<<<grid, 320>>>(X, Y, dr, w, (float*)d_out);
}

// round 7
// speedup vs baseline: 1.0494x; 1.0494x over previous
#include <cuda_runtime.h>

// SSIM loss: B=64, C=2, H=W=320, WIN=7 (VALID), channel-summing uniform window.
// out = 1 - mean(S), S per output pixel [64,1,314,314].
// Flattened grid: 444 blocks (=148 SMs x 3 CTAs), each takes 45-46 of the
// 20096 global output rows; a block crosses a batch boundary at most once.

#define Hh 320
#define Ww 320
#define OH 314
#define OW 314
#define Bb 64
#define NBLOCKS 444
#define TOTROWS (Bb * OH)                 // 20096
#define BASE_ROWS (TOTROWS / NBLOCKS)     // 45
#define REM_ROWS (TOTROWS % NBLOCKS)      // 116
#define NPIX (64.0 * 314.0 * 314.0)
#define GROUP 4
#define CH_OFF (Hh * Ww)                  // channel stride (102400)

__device__ float g_partials[NBLOCKS];
__device__ unsigned int g_count = 0;

__global__ __launch_bounds__(320, 3) void ssim_main(
    const float* __restrict__ X, const float* __restrict__ Y,
    const float* __restrict__ data_range, const float* __restrict__ w,
    float* __restrict__ out) {
    const int t = threadIdx.x;        // input column 0..319
    const int bid = blockIdx.x;       // 0..443

    const int start = bid * BASE_ROWS + min(bid, REM_ROWS);
    int left = BASE_ROWS + (bid < REM_ROWS ? 1 : 0);
    int row = start;                  // global output row

    const float w0 = w[0];            // uniform weight (1/49)
    const float cn = 49.0f / 48.0f;   // COV_NORM

    __shared__ __align__(16) float sm[GROUP][5][336];
    __shared__ float red[320];
    __shared__ int s_islast;

    // zero the pad region of sm once (read by tail float4 loads)
    if (t < 16) {
#pragma unroll
        for (int r = 0; r < GROUP; ++r)
#pragma unroll
            for (int s = 0; s < 5; ++s) sm[r][s][320 + t] = 0.0f;
    }
    __syncthreads();

    const int hr = t / 80;            // horizontal-phase row within group
    const int hj = t % 80;
    const int c0 = hj * 4;            // horizontal-phase base column

    float acc = 0.0f;

#pragma unroll 1
    while (left > 0) {
        const int b = row / OH;
        const int y0 = row - b * OH;
        const int seg = min(left, OH - y0);

        const float dr = data_range[b];
        const float C1 = (0.01f * dr) * (0.01f * dr);
        const float C2 = (0.03f * dr) * (0.03f * dr);

        const float* __restrict__ Xb = X + (size_t)b * 2 * CH_OFF;
        const float* __restrict__ Yb = Y + (size_t)b * 2 * CH_OFF;

        // 8-slot ring of RAW inputs; row k's data lives at slot k&7 (static).
        float rx0[8], rx1[8], rya[8], ryb[8];
        float vsum[5];
#pragma unroll
        for (int s = 0; s < 5; ++s) vsum[s] = 0.0f;

        // prologue: input rows y0..y0+5 -> slots 0..5 (MLP 24)
        {
            int off = y0 * Ww + t;
#pragma unroll
            for (int r = 0; r < 6; ++r) {
                float x0 = Xb[off], x1 = Xb[off + CH_OFF];
                float ya = Yb[off], yb = Yb[off + CH_OFF];
                rx0[r] = x0; rx1[r] = x1; rya[r] = ya; ryb[r] = yb;
                vsum[0] += x0 + x1;
                vsum[1] += ya + yb;
                vsum[2] += fmaf(x0, x0, x1 * x1);
                vsum[3] += fmaf(ya, ya, yb * yb);
                vsum[4] += fmaf(x0, ya, x1 * yb);
                off += Ww;
            }
        }

        const int P = (seg + 7) / 8;
        int offn = (y0 + 6) * Ww + t;   // running offset of next new input row

#pragma unroll 1
        for (int p = 0; p < P; ++p) {
#pragma unroll
            for (int half = 0; half < 2; ++half) {
                // ---- group loads: up to 4 rows x 4 values (MLP 16) ----
                float g4[GROUP][4];
#pragma unroll
                for (int r = 0; r < GROUP; ++r) {
                    const int k = 8 * p + half * 4 + r;
                    if (k < seg) {
                        const int off = offn + r * Ww;
                        g4[r][0] = Xb[off]; g4[r][1] = Xb[off + CH_OFF];
                        g4[r][2] = Yb[off]; g4[r][3] = Yb[off + CH_OFF];
                    } else {
                        g4[r][0] = g4[r][1] = g4[r][2] = g4[r][3] = 0.0f;
                    }
                }
                offn += 4 * Ww;

                // ---- vertical phase: column sums (static ring slots) ----
#pragma unroll
                for (int r = 0; r < GROUP; ++r) {
                    const int u = half * 4 + r;      // k mod 8 (static)
                    const int k = 8 * p + u;
                    if (k < seg) {
                        float x0 = g4[r][0], x1 = g4[r][1];
                        float ya = g4[r][2], yb = g4[r][3];
                        vsum[0] += x0 + x1;
                        vsum[1] += ya + yb;
                        vsum[2] += fmaf(x0, x0, x1 * x1);
                        vsum[3] += fmaf(ya, ya, yb * yb);
                        vsum[4] += fmaf(x0, ya, x1 * yb);
                        sm[r][0][t] = vsum[0];
                        sm[r][1][t] = vsum[1];
                        sm[r][2][t] = vsum[2];
                        sm[r][3][t] = vsum[3];
                        sm[r][4][t] = vsum[4];
                        // retire row k (slot u), append row k+6 (slot (u+6)&7)
                        const int SO = u;                // static
                        const int SN = (u + 6) & 7;      // static
                        float o0 = rx0[SO], o1 = rx1[SO];
                        float oa = rya[SO], ob = ryb[SO];
                        vsum[0] -= o0 + o1;
                        vsum[1] -= oa + ob;
                        vsum[2] -= fmaf(o0, o0, o1 * o1);
                        vsum[3] -= fmaf(oa, oa, ob * ob);
                        vsum[4] -= fmaf(o0, oa, o1 * ob);
                        rx0[SN] = x0; rx1[SN] = x1;
                        rya[SN] = ya; ryb[SN] = yb;
                    }
                }

                __syncthreads();   // column sums visible

                // ---- horizontal: all 320 threads (4 rows x 80 col-groups) ----
                {
                    const int k = 8 * p + half * 4 + hr;
                    if (k < seg) {
                        float h[5][4];
#pragma unroll
                        for (int s = 0; s < 5; ++s) {
                            const float4 va = *(const float4*)&sm[hr][s][c0];
                            const float4 vb = *(const float4*)&sm[hr][s][c0 + 4];
                            const float4 vc = *(const float4*)&sm[hr][s][c0 + 8];
                            float h0 = va.x + va.y + va.z + va.w + vb.x + vb.y + vb.z;
                            float h1 = h0 - va.x + vb.w;
                            float h2 = h1 - va.y + vc.x;
                            float h3 = h2 - va.z + vc.y;
                            h[s][0] = h0; h[s][1] = h1; h[s][2] = h2; h[s][3] = h3;
                        }
#pragma unroll
                        for (int i = 0; i < 4; ++i) {
                            if (c0 + i < OW) {
                                float ux  = w0 * h[0][i];
                                float uy  = w0 * h[1][i];
                                float uxx = w0 * h[2][i];
                                float uyy = w0 * h[3][i];
                                float uxy = w0 * h[4][i];
                                float vx  = cn * (uxx - ux * ux);
                                float vy  = cn * (uyy - uy * uy);
                                float vxy = cn * (uxy - ux * uy);
                                float A1 = 2.0f * ux * uy + C1;
                                float A2 = 2.0f * vxy + C2;
                                float B1 = ux * ux + uy * uy + C1;
                                float B2 = vx + vy + C2;
                                acc += __fdividef(A1 * A2, B1 * B2);
                            }
                        }
                    }
                }

                __syncthreads();   // reads done before next vertical writes
            }
        }

        row += seg;
        left -= seg;
    }

    // ---- block reduction of acc (fixed order -> deterministic) ----
    red[t] = acc;
    __syncthreads();
    if (t < 160) red[t] += red[t + 160];
    __syncthreads();
    if (t < 80) red[t] += red[t + 80];
    __syncthreads();
    if (t < 40) red[t] += red[t + 40];
    __syncthreads();
    if (t < 20) red[t] += red[t + 20];
    __syncthreads();
    if (t < 10) red[t] += red[t + 10];
    __syncthreads();
    if (t < 5) red[t] += red[t + 5];
    __syncthreads();

    if (t == 0) {
        float v = red[0] + red[1] + red[2] + red[3] + red[4];
        g_partials[bid] = v;
        __threadfence();
        unsigned int old = atomicAdd(&g_count, 1u);
        s_islast = (old == NBLOCKS - 1);
    }
    __syncthreads();

    // ---- last block finishes the global reduction (deterministic order) ----
    if (s_islast) {
        __threadfence();
        float v = g_partials[t];
        if (t < NBLOCKS - 320) v += g_partials[t + 320];
        red[t] = v;
        __syncthreads();
        if (t < 160) red[t] += red[t + 160];
        __syncthreads();
        if (t < 80) red[t] += red[t + 80];
        __syncthreads();
        if (t < 40) red[t] += red[t + 40];
        __syncthreads();
        if (t < 20) red[t] += red[t + 20];
        __syncthreads();
        if (t < 10) red[t] += red[t + 10];
        __syncthreads();
        if (t < 5) red[t] += red[t + 5];
        __syncthreads();
        if (t == 0) {
            double total = (double)(red[0] + red[1] + red[2] + red[3] + red[4]);
            out[0] = (float)(1.0 - total / NPIX);
            g_count = 0;   // reset for next graph replay
        }
    }
}

extern "C" void kernel_launch(void* const* d_in, const int* in_sizes, int n_in,
                              void* d_out, int out_size) {
    const float* X  = (const float*)d_in[0];
    const float* Y  = (const float*)d_in[1];
    const float* dr = (const float*)d_in[2];
    const float* w  = (const float*)d_in[3];
    ssim_main<<<NBLOCKS, 320>>>(X, Y, dr, w, (float*)d_out);
}